// round 1
// baseline (speedup 1.0000x reference)
#include <cuda_runtime.h>
#include <math_constants.h>

#define BATCH  4
#define SEQ    2048
#define DMODEL 1024
#define NHEAD  16
#define DKH    64
#define MROWS  (BATCH*SEQ)   // 8192

// Scratch (allocation-free rule: __device__ globals)
__device__ float g_q[MROWS*DMODEL];
__device__ float g_k[MROWS*DMODEL];
__device__ float g_v[MROWS*DMODEL];
__device__ float g_ctx[MROWS*DMODEL];

// ---------------------------------------------------------------------------
// GEMM: C[M,N] = A[M,K] @ W[N,K]^T + bias[N]   (nn.Linear semantics)
// M=8192, N=1024, K=1024. 128x128x8 tiles, 8x8 per thread, 256 threads.
// ---------------------------------------------------------------------------
__device__ __forceinline__ void gemm_body(const float* __restrict__ A,
                                          const float* __restrict__ W,
                                          const float* __restrict__ bias,
                                          float* __restrict__ C)
{
    const int N = DMODEL, K = DMODEL;
    __shared__ float As[8][128];
    __shared__ float Ws[8][128];

    const int tid = threadIdx.x;
    const int bm  = blockIdx.y * 128;
    const int bn  = blockIdx.x * 128;
    const int tx  = tid & 15;        // 0..15 -> cols tx*8..+7
    const int ty  = tid >> 4;        // 0..15 -> rows ty*8..+7
    const int lr  = tid >> 1;        // 0..127 load row
    const int lc  = (tid & 1) * 4;   // 0 or 4 load col

    float acc[8][8];
    #pragma unroll
    for (int i = 0; i < 8; i++)
        #pragma unroll
        for (int j = 0; j < 8; j++) acc[i][j] = 0.f;

    const float* Ap = A + (bm + lr) * K + lc;
    const float* Wp = W + (bn + lr) * K + lc;

    for (int k0 = 0; k0 < K; k0 += 8) {
        float4 av = *(const float4*)(Ap + k0);
        float4 wv = *(const float4*)(Wp + k0);
        __syncthreads();
        As[lc+0][lr] = av.x; As[lc+1][lr] = av.y; As[lc+2][lr] = av.z; As[lc+3][lr] = av.w;
        Ws[lc+0][lr] = wv.x; Ws[lc+1][lr] = wv.y; Ws[lc+2][lr] = wv.z; Ws[lc+3][lr] = wv.w;
        __syncthreads();
        #pragma unroll
        for (int kk = 0; kk < 8; kk++) {
            float4 a0 = *(const float4*)&As[kk][ty*8];
            float4 a1 = *(const float4*)&As[kk][ty*8+4];
            float4 b0 = *(const float4*)&Ws[kk][tx*8];
            float4 b1 = *(const float4*)&Ws[kk][tx*8+4];
            float a[8] = {a0.x,a0.y,a0.z,a0.w,a1.x,a1.y,a1.z,a1.w};
            float b[8] = {b0.x,b0.y,b0.z,b0.w,b1.x,b1.y,b1.z,b1.w};
            #pragma unroll
            for (int i = 0; i < 8; i++)
                #pragma unroll
                for (int j = 0; j < 8; j++)
                    acc[i][j] += a[i] * b[j];
        }
    }

    #pragma unroll
    for (int i = 0; i < 8; i++) {
        int r = bm + ty*8 + i;
        #pragma unroll
        for (int j = 0; j < 8; j += 4) {
            int c = bn + tx*8 + j;
            float4 bv = *(const float4*)(bias + c);
            float4 ov;
            ov.x = acc[i][j+0] + bv.x;
            ov.y = acc[i][j+1] + bv.y;
            ov.z = acc[i][j+2] + bv.z;
            ov.w = acc[i][j+3] + bv.w;
            *(float4*)(C + (size_t)r * N + c) = ov;
        }
    }
}

__global__ void __launch_bounds__(256)
qkv_gemm_kernel(const float* __restrict__ x,
                const float* __restrict__ Wq, const float* __restrict__ bq,
                const float* __restrict__ Wk, const float* __restrict__ bk,
                const float* __restrict__ Wv, const float* __restrict__ bv)
{
    const float* W; const float* bias; float* C;
    if (blockIdx.z == 0)      { W = Wq; bias = bq; C = g_q; }
    else if (blockIdx.z == 1) { W = Wk; bias = bk; C = g_k; }
    else                      { W = Wv; bias = bv; C = g_v; }
    gemm_body(x, W, bias, C);
}

__global__ void __launch_bounds__(256)
out_gemm_kernel(const float* __restrict__ Wo, const float* __restrict__ bo,
                float* __restrict__ out)
{
    gemm_body(g_ctx, Wo, bo, out);
}

// ---------------------------------------------------------------------------
// Flash attention (causal). One block per (q-tile of 64, head, batch).
// 256 threads: thread t owns row = t/4, score cols {cg+4j} (cg = t%4),
// and output d-slice cg*16..cg*16+15. K/V tiles of 32 rows.
// Static smem: Qs 64x68 + Ks 32x68 + Vs 32x68 + Ps 64x33 = 43264 B.
// ---------------------------------------------------------------------------
#define QSTR 68
#define KSTR 68
#define PSTR 33

__global__ void __launch_bounds__(256) attn_kernel()
{
    __shared__ float Qs[64*QSTR];
    __shared__ float Ks[32*KSTR];
    __shared__ float Vs[32*KSTR];
    __shared__ float Ps[64*PSTR];

    const int b  = blockIdx.z;
    const int h  = blockIdx.y;
    const int qt = blockIdx.x;
    const int q0 = qt * 64;
    const int tid = threadIdx.x;
    const int row = tid >> 2;      // 0..63
    const int cg  = tid & 3;       // 0..3
    const int dbase = cg * 16;

    // Load Q tile, pre-scaled by 1/sqrt(dk) = 0.125
    #pragma unroll
    for (int it = 0; it < 4; it++) {
        int e  = tid + it * 256;       // 0..1023 float4s
        int r  = e >> 4;
        int c4 = (e & 15) << 2;
        float4 v = *(const float4*)&g_q[(b*SEQ + q0 + r)*DMODEL + h*DKH + c4];
        v.x *= 0.125f; v.y *= 0.125f; v.z *= 0.125f; v.w *= 0.125f;
        *(float4*)&Qs[r*QSTR + c4] = v;
    }

    float m_i = -CUDART_INF_F;
    float l_i = 0.f;
    float o[16];
    #pragma unroll
    for (int u = 0; u < 16; u++) o[u] = 0.f;

    const int ntiles = 2 * (qt + 1);     // KV rows up to q0+63 inclusive
    for (int kt = 0; kt < ntiles; kt++) {
        const int k0 = kt * 32;
        __syncthreads();
        #pragma unroll
        for (int it = 0; it < 2; it++) {
            int e  = tid + it * 256;     // 0..511 float4s (32x16)
            int r  = e >> 4;
            int c4 = (e & 15) << 2;
            int g  = (b*SEQ + k0 + r)*DMODEL + h*DKH + c4;
            *(float4*)&Ks[r*KSTR + c4] = *(const float4*)&g_k[g];
            *(float4*)&Vs[r*KSTR + c4] = *(const float4*)&g_v[g];
        }
        __syncthreads();

        // Scores for this thread's 8 columns (col = cg + 4j)
        float s[8];
        #pragma unroll
        for (int j = 0; j < 8; j++) s[j] = 0.f;
        #pragma unroll 4
        for (int kk = 0; kk < 64; kk += 4) {
            float4 q4 = *(const float4*)&Qs[row*QSTR + kk];
            #pragma unroll
            for (int j = 0; j < 8; j++) {
                float4 k4 = *(const float4*)&Ks[(cg + 4*j)*KSTR + kk];
                s[j] += q4.x*k4.x + q4.y*k4.y + q4.z*k4.z + q4.w*k4.w;
            }
        }

        // Causal mask
        #pragma unroll
        for (int j = 0; j < 8; j++) {
            int colg = k0 + cg + 4*j;
            if (colg > q0 + row) s[j] = -CUDART_INF_F;
        }

        // Online softmax (row group = 4 consecutive lanes)
        float tmax = s[0];
        #pragma unroll
        for (int j = 1; j < 8; j++) tmax = fmaxf(tmax, s[j]);
        tmax = fmaxf(tmax, __shfl_xor_sync(0xffffffffu, tmax, 1));
        tmax = fmaxf(tmax, __shfl_xor_sync(0xffffffffu, tmax, 2));
        float mnew = fmaxf(m_i, tmax);
        float corr = __expf(m_i - mnew);   // 0 on first tile (m_i = -inf)
        float psum = 0.f;
        #pragma unroll
        for (int j = 0; j < 8; j++) {
            float p = __expf(s[j] - mnew);
            s[j] = p;
            psum += p;
        }
        psum += __shfl_xor_sync(0xffffffffu, psum, 1);
        psum += __shfl_xor_sync(0xffffffffu, psum, 2);
        l_i = l_i * corr + psum;
        m_i = mnew;
        #pragma unroll
        for (int u = 0; u < 16; u++) o[u] *= corr;

        // Exchange P within the row's 4 lanes via smem
        #pragma unroll
        for (int j = 0; j < 8; j++) Ps[row*PSTR + cg + 4*j] = s[j];
        __syncwarp();

        // O += P @ V  (this thread's 16-wide d slice)
        #pragma unroll 4
        for (int j = 0; j < 32; j++) {
            float p = Ps[row*PSTR + j];
            const float* vp = &Vs[j*KSTR + dbase];
            float4 v0 = *(const float4*)(vp);
            float4 v1 = *(const float4*)(vp + 4);
            float4 v2 = *(const float4*)(vp + 8);
            float4 v3 = *(const float4*)(vp + 12);
            o[0]  += p*v0.x; o[1]  += p*v0.y; o[2]  += p*v0.z; o[3]  += p*v0.w;
            o[4]  += p*v1.x; o[5]  += p*v1.y; o[6]  += p*v1.z; o[7]  += p*v1.w;
            o[8]  += p*v2.x; o[9]  += p*v2.y; o[10] += p*v2.z; o[11] += p*v2.w;
            o[12] += p*v3.x; o[13] += p*v3.y; o[14] += p*v3.z; o[15] += p*v3.w;
        }
        __syncwarp();
    }

    const float inv = 1.0f / l_i;
    const int gbase = (b*SEQ + q0 + row)*DMODEL + h*DKH + dbase;
    #pragma unroll
    for (int u = 0; u < 16; u += 4) {
        float4 ov = make_float4(o[u]*inv, o[u+1]*inv, o[u+2]*inv, o[u+3]*inv);
        *(float4*)&g_ctx[gbase + u] = ov;
    }
}

// ---------------------------------------------------------------------------
extern "C" void kernel_launch(void* const* d_in, const int* in_sizes, int n_in,
                              void* d_out, int out_size)
{
    const float* x  = (const float*)d_in[0];
    const float* Wq = (const float*)d_in[1];
    const float* bq = (const float*)d_in[2];
    const float* Wk = (const float*)d_in[3];
    const float* bk = (const float*)d_in[4];
    const float* Wv = (const float*)d_in[5];
    const float* bv = (const float*)d_in[6];
    const float* Wo = (const float*)d_in[7];
    const float* bo = (const float*)d_in[8];
    float* out = (float*)d_out;

    dim3 gq(DMODEL/128, MROWS/128, 3);
    qkv_gemm_kernel<<<gq, 256>>>(x, Wq, bq, Wk, bk, Wv, bv);

    dim3 ga(SEQ/64, NHEAD, BATCH);
    attn_kernel<<<ga, 256>>>();

    dim3 go(DMODEL/128, MROWS/128, 1);
    out_gemm_kernel<<<go, 256>>>(Wo, bo, out);
}

// round 5
// speedup vs baseline: 1.9517x; 1.9517x over previous
#include <cuda_runtime.h>
#include <math_constants.h>

#define BATCH  4
#define SEQ    2048
#define DMODEL 1024
#define NHEAD  16
#define DKH    64
#define MROWS  (BATCH*SEQ)   // 8192

// Scratch (__device__ globals: allocation-free rule)
// Q and K are stored TRANSPOSED per-head: g_qT[(b*1024 + c)*2048 + s]
// where c = h*64 + dh (d_model column), s = position within sequence.
__device__ float g_qT[DMODEL*MROWS];
__device__ float g_kT[DMODEL*MROWS];
__device__ float g_v [MROWS*DMODEL];
__device__ float g_ctx[MROWS*DMODEL];

// ---------------------------------------------------------------------------
// Double-buffered GEMM core: acc[8][8] += A[128xK] @ W[128xK]^T  (tile at bm,bn)
// 256 threads, 128x128x8 tiles, one __syncthreads per k-step.
// ---------------------------------------------------------------------------
__device__ __forceinline__ void gemm_mm(const float* __restrict__ A,
                                        const float* __restrict__ W,
                                        float (&acc)[8][8])
{
    __shared__ float As[2][8][128];
    __shared__ float Ws[2][8][128];

    const int tid = threadIdx.x;
    const int bm  = blockIdx.y * 128;
    const int bn  = blockIdx.x * 128;
    const int tx  = tid & 15;
    const int ty  = tid >> 4;
    const int lr  = tid >> 1;
    const int lc  = (tid & 1) * 4;

    const float* Ap = A + (size_t)(bm + lr) * DMODEL + lc;
    const float* Wp = W + (size_t)(bn + lr) * DMODEL + lc;

    // prologue: fill buffer 0
    float4 av = *(const float4*)(Ap);
    float4 wv = *(const float4*)(Wp);
    As[0][lc+0][lr]=av.x; As[0][lc+1][lr]=av.y; As[0][lc+2][lr]=av.z; As[0][lc+3][lr]=av.w;
    Ws[0][lc+0][lr]=wv.x; Ws[0][lc+1][lr]=wv.y; Ws[0][lc+2][lr]=wv.z; Ws[0][lc+3][lr]=wv.w;
    __syncthreads();

    int cur = 0;
    for (int k0 = 0; k0 < DMODEL; k0 += 8) {
        const bool more = (k0 + 8 < DMODEL);
        if (more) {
            av = *(const float4*)(Ap + k0 + 8);
            wv = *(const float4*)(Wp + k0 + 8);
        }
        #pragma unroll
        for (int kk = 0; kk < 8; kk++) {
            float4 a0 = *(const float4*)&As[cur][kk][ty*8];
            float4 a1 = *(const float4*)&As[cur][kk][ty*8+4];
            float4 b0 = *(const float4*)&Ws[cur][kk][tx*8];
            float4 b1 = *(const float4*)&Ws[cur][kk][tx*8+4];
            float a[8] = {a0.x,a0.y,a0.z,a0.w,a1.x,a1.y,a1.z,a1.w};
            float b[8] = {b0.x,b0.y,b0.z,b0.w,b1.x,b1.y,b1.z,b1.w};
            #pragma unroll
            for (int i = 0; i < 8; i++)
                #pragma unroll
                for (int j = 0; j < 8; j++)
                    acc[i][j] += a[i] * b[j];
        }
        if (more) {
            const int nb = cur ^ 1;
            As[nb][lc+0][lr]=av.x; As[nb][lc+1][lr]=av.y; As[nb][lc+2][lr]=av.z; As[nb][lc+3][lr]=av.w;
            Ws[nb][lc+0][lr]=wv.x; Ws[nb][lc+1][lr]=wv.y; Ws[nb][lc+2][lr]=wv.z; Ws[nb][lc+3][lr]=wv.w;
        }
        __syncthreads();
        cur ^= 1;
    }
}

// QKV projections. z=0 -> Q (transposed store, pre-scaled by 1/8),
// z=1 -> K (transposed store), z=2 -> V (row-major store).
__global__ void __launch_bounds__(256, 2)
qkv_gemm_kernel(const float* __restrict__ x,
                const float* __restrict__ Wq, const float* __restrict__ bq,
                const float* __restrict__ Wk, const float* __restrict__ bk,
                const float* __restrict__ Wv, const float* __restrict__ bv)
{
    const int z = blockIdx.z;
    const float* W    = (z == 0) ? Wq : (z == 1) ? Wk : Wv;
    const float* bias = (z == 0) ? bq : (z == 1) ? bk : bv;

    float acc[8][8];
    #pragma unroll
    for (int i = 0; i < 8; i++)
        #pragma unroll
        for (int j = 0; j < 8; j++) acc[i][j] = 0.f;

    gemm_mm(x, W, acc);

    const int tx = threadIdx.x & 15, ty = threadIdx.x >> 4;
    const int bm = blockIdx.y * 128, bn = blockIdx.x * 128;

    if (z == 2) {
        #pragma unroll
        for (int i = 0; i < 8; i++) {
            int r = bm + ty*8 + i;
            #pragma unroll
            for (int j = 0; j < 8; j += 4) {
                int c = bn + tx*8 + j;
                float4 bv4 = *(const float4*)(bias + c);
                float4 ov = make_float4(acc[i][j]+bv4.x, acc[i][j+1]+bv4.y,
                                        acc[i][j+2]+bv4.z, acc[i][j+3]+bv4.w);
                *(float4*)&g_v[(size_t)r * DMODEL + c] = ov;
            }
        }
    } else {
        float* dst = (z == 0) ? g_qT : g_kT;
        const float scale = (z == 0) ? 0.125f : 1.0f;
        #pragma unroll
        for (int i = 0; i < 8; i++) {
            int r = bm + ty*8 + i;
            int b = r >> 11, s = r & (SEQ-1);
            #pragma unroll
            for (int j = 0; j < 8; j++) {
                int c = bn + tx*8 + j;
                float v = (acc[i][j] + bias[c]) * scale;
                dst[((size_t)(b*1024 + c))*SEQ + s] = v;
            }
        }
    }
}

__global__ void __launch_bounds__(256, 2)
out_gemm_kernel(const float* __restrict__ Wo, const float* __restrict__ bo,
                float* __restrict__ out)
{
    float acc[8][8];
    #pragma unroll
    for (int i = 0; i < 8; i++)
        #pragma unroll
        for (int j = 0; j < 8; j++) acc[i][j] = 0.f;

    gemm_mm(g_ctx, Wo, acc);

    const int tx = threadIdx.x & 15, ty = threadIdx.x >> 4;
    const int bm = blockIdx.y * 128, bn = blockIdx.x * 128;
    #pragma unroll
    for (int i = 0; i < 8; i++) {
        int r = bm + ty*8 + i;
        #pragma unroll
        for (int j = 0; j < 8; j += 4) {
            int c = bn + tx*8 + j;
            float4 bv4 = *(const float4*)(bo + c);
            float4 ov = make_float4(acc[i][j]+bv4.x, acc[i][j+1]+bv4.y,
                                    acc[i][j+2]+bv4.z, acc[i][j+3]+bv4.w);
            *(float4*)&out[(size_t)r * DMODEL + c] = ov;
        }
    }
}

// ---------------------------------------------------------------------------
// Flash attention as two register-tiled GEMMs.
// Block = (qpair, head, batch); processes q-tiles qp and 31-qp (33 kv iters).
// 256 threads: tx = tid&15 (cols / d-slice), ty = tid>>4 (rows). 4x4 micro.
// smem: Qs[64][64] k-major, KPs[64][64] (K k-major, then P row-major), Vs[64][64].
// Total 48KB static. 2 CTAs/SM.
// ---------------------------------------------------------------------------
__global__ void __launch_bounds__(256, 2) attn_kernel()
{
    __shared__ float Qs [64*64];
    __shared__ float KPs[64*64];
    __shared__ float Vs [64*64];

    const int b  = blockIdx.z;
    const int h  = blockIdx.y;
    const int qp = blockIdx.x;           // 0..15
    const int tid = threadIdx.x;
    const int tx  = tid & 15;
    const int ty  = tid >> 4;
    const int tx4 = tx * 4;
    const int ty4 = ty * 4;

    const size_t headQT = (size_t)(b*1024 + h*DKH) * SEQ;   // base into g_qT/g_kT
    const size_t headV  = (size_t)(b*SEQ) * DMODEL + h*DKH;

    for (int half = 0; half < 2; half++) {
        const int qt = half ? (31 - qp) : qp;
        const int q0 = qt * 64;

        __syncthreads();   // previous half done with Qs
        // Load Q tile (k-major, already pre-scaled by 1/8): Qs[kk][row]
        #pragma unroll
        for (int it = 0; it < 4; it++) {
            int e  = tid + it * 256;
            int kk = e >> 4;
            int c4 = (e & 15) << 2;
            *(float4*)&Qs[kk*64 + c4] =
                *(const float4*)&g_qT[headQT + (size_t)kk*SEQ + q0 + c4];
        }

        float m[4], l[4], o[4][4];
        #pragma unroll
        for (int i = 0; i < 4; i++) {
            m[i] = -CUDART_INF_F; l[i] = 0.f;
            #pragma unroll
            for (int j = 0; j < 4; j++) o[i][j] = 0.f;
        }

        const int ntiles = qt + 1;
        for (int kt = 0; kt < ntiles; kt++) {
            const int k0 = kt * 64;
            __syncthreads();   // prev PV done with KPs/Vs; Q stores visible
            // Load K (k-major) and V (row-major)
            #pragma unroll
            for (int it = 0; it < 4; it++) {
                int e  = tid + it * 256;
                int r  = e >> 4;
                int c4 = (e & 15) << 2;
                *(float4*)&KPs[r*64 + c4] =
                    *(const float4*)&g_kT[headQT + (size_t)r*SEQ + k0 + c4];
                *(float4*)&Vs[r*64 + c4] =
                    *(const float4*)&g_v[headV + (size_t)(k0 + r)*DMODEL + c4];
            }
            __syncthreads();

            // S = Q @ K^T  (outer product over kk)
            float s[4][4];
            #pragma unroll
            for (int i = 0; i < 4; i++)
                #pragma unroll
                for (int j = 0; j < 4; j++) s[i][j] = 0.f;

            #pragma unroll 8
            for (int kk = 0; kk < 64; kk++) {
                float4 q4 = *(const float4*)&Qs [kk*64 + ty4];
                float4 k4 = *(const float4*)&KPs[kk*64 + tx4];
                float qa[4] = {q4.x, q4.y, q4.z, q4.w};
                float ka[4] = {k4.x, k4.y, k4.z, k4.w};
                #pragma unroll
                for (int i = 0; i < 4; i++)
                    #pragma unroll
                    for (int j = 0; j < 4; j++)
                        s[i][j] += qa[i] * ka[j];
            }

            // Causal mask (diagonal tile only: k0 == q0)
            if (kt == qt) {
                #pragma unroll
                for (int i = 0; i < 4; i++)
                    #pragma unroll
                    for (int j = 0; j < 4; j++)
                        if (tx4 + j > ty4 + i) s[i][j] = -CUDART_INF_F;
            }

            // Online softmax per row (reduce across the 16 tx lanes)
            #pragma unroll
            for (int i = 0; i < 4; i++) {
                float mx = fmaxf(fmaxf(s[i][0], s[i][1]), fmaxf(s[i][2], s[i][3]));
                mx = fmaxf(mx, __shfl_xor_sync(0xffffffffu, mx, 1));
                mx = fmaxf(mx, __shfl_xor_sync(0xffffffffu, mx, 2));
                mx = fmaxf(mx, __shfl_xor_sync(0xffffffffu, mx, 4));
                mx = fmaxf(mx, __shfl_xor_sync(0xffffffffu, mx, 8));
                float mnew = fmaxf(m[i], mx);
                float corr = __expf(m[i] - mnew);
                float sum = 0.f;
                #pragma unroll
                for (int j = 0; j < 4; j++) {
                    float p = __expf(s[i][j] - mnew);
                    s[i][j] = p;
                    sum += p;
                }
                sum += __shfl_xor_sync(0xffffffffu, sum, 1);
                sum += __shfl_xor_sync(0xffffffffu, sum, 2);
                sum += __shfl_xor_sync(0xffffffffu, sum, 4);
                sum += __shfl_xor_sync(0xffffffffu, sum, 8);
                l[i] = l[i] * corr + sum;
                m[i] = mnew;
                #pragma unroll
                for (int j = 0; j < 4; j++) o[i][j] *= corr;
            }

            __syncthreads();   // all S-GEMM reads of KPs (K) complete
            // Write P over the K tile: KPs[row][col]
            #pragma unroll
            for (int i = 0; i < 4; i++)
                *(float4*)&KPs[(ty4 + i)*64 + tx4] =
                    make_float4(s[i][0], s[i][1], s[i][2], s[i][3]);
            __syncthreads();

            // O += P @ V
            #pragma unroll 4
            for (int c4i = 0; c4i < 16; c4i++) {
                const int kk0 = c4i * 4;
                float4 p0 = *(const float4*)&KPs[(ty4+0)*64 + kk0];
                float4 p1 = *(const float4*)&KPs[(ty4+1)*64 + kk0];
                float4 p2 = *(const float4*)&KPs[(ty4+2)*64 + kk0];
                float4 p3 = *(const float4*)&KPs[(ty4+3)*64 + kk0];
                float pr[4][4] = {{p0.x,p0.y,p0.z,p0.w},{p1.x,p1.y,p1.z,p1.w},
                                  {p2.x,p2.y,p2.z,p2.w},{p3.x,p3.y,p3.z,p3.w}};
                #pragma unroll
                for (int c = 0; c < 4; c++) {
                    float4 v4 = *(const float4*)&Vs[(kk0+c)*64 + tx4];
                    float va[4] = {v4.x, v4.y, v4.z, v4.w};
                    #pragma unroll
                    for (int i = 0; i < 4; i++)
                        #pragma unroll
                        for (int j = 0; j < 4; j++)
                            o[i][j] += pr[i][c] * va[j];
                }
            }
        }

        // Epilogue: normalize and store context
        #pragma unroll
        for (int i = 0; i < 4; i++) {
            float inv = 1.0f / l[i];
            float4 ov = make_float4(o[i][0]*inv, o[i][1]*inv, o[i][2]*inv, o[i][3]*inv);
            *(float4*)&g_ctx[(size_t)(b*SEQ + q0 + ty4 + i)*DMODEL + h*DKH + tx4] = ov;
        }
    }
}

// ---------------------------------------------------------------------------
extern "C" void kernel_launch(void* const* d_in, const int* in_sizes, int n_in,
                              void* d_out, int out_size)
{
    const float* x  = (const float*)d_in[0];
    const float* Wq = (const float*)d_in[1];
    const float* bq = (const float*)d_in[2];
    const float* Wk = (const float*)d_in[3];
    const float* bk = (const float*)d_in[4];
    const float* Wv = (const float*)d_in[5];
    const float* bv = (const float*)d_in[6];
    const float* Wo = (const float*)d_in[7];
    const float* bo = (const float*)d_in[8];
    float* out = (float*)d_out;

    dim3 gq(DMODEL/128, MROWS/128, 3);
    qkv_gemm_kernel<<<gq, 256>>>(x, Wq, bq, Wk, bk, Wv, bv);

    dim3 ga(16, NHEAD, BATCH);
    attn_kernel<<<ga, 256>>>();

    dim3 go(DMODEL/128, MROWS/128, 1);
    out_gemm_kernel<<<go, 256>>>(Wo, bo, out);
}

// round 13
// speedup vs baseline: 3.0925x; 1.5846x over previous
#include <cuda_runtime.h>
#include <cuda_bf16.h>
#include <math_constants.h>
#include <cstdint>

#define BATCH  4
#define SEQ    2048
#define DMODEL 1024
#define NHEAD  16
#define DKH    64
#define MROWS  (BATCH*SEQ)   // 8192

// Scratch (__device__ globals: allocation-free rule)
// Q and K stored TRANSPOSED per-head: g_qT[(b*1024 + c)*2048 + s]
__device__ float g_qT[DMODEL*MROWS];
__device__ float g_kT[DMODEL*MROWS];
__device__ float g_v [MROWS*DMODEL];
__device__ float g_ctx[MROWS*DMODEL];

// ===========================================================================
// Warp-level MMA helpers (sm_80+ baseline PTX; family-safe on sm_103)
// ===========================================================================
__device__ __forceinline__ uint32_t smem_u32(const void* p) {
    uint32_t a;
    asm("{ .reg .u64 t; cvta.to.shared.u64 t, %1; cvt.u32.u64 %0, t; }"
        : "=r"(a) : "l"(p));
    return a;
}
__device__ __forceinline__ void ldsm4(uint32_t* r, uint32_t addr) {
    asm volatile("ldmatrix.sync.aligned.m8n8.x4.shared.b16 {%0,%1,%2,%3}, [%4];"
        : "=r"(r[0]), "=r"(r[1]), "=r"(r[2]), "=r"(r[3]) : "r"(addr));
}
__device__ __forceinline__ void mma16816(float* c, const uint32_t* a,
                                         uint32_t b0, uint32_t b1) {
    asm volatile(
        "mma.sync.aligned.m16n8k16.row.col.f32.bf16.bf16.f32 "
        "{%0,%1,%2,%3}, {%4,%5,%6,%7}, {%8,%9}, {%0,%1,%2,%3};"
        : "+f"(c[0]), "+f"(c[1]), "+f"(c[2]), "+f"(c[3])
        : "r"(a[0]), "r"(a[1]), "r"(a[2]), "r"(a[3]), "r"(b0), "r"(b1));
}

__device__ __forceinline__ uint32_t pk2(__nv_bfloat16 a, __nv_bfloat16 b) {
    return (uint32_t)__bfloat16_as_ushort(a) | ((uint32_t)__bfloat16_as_ushort(b) << 16);
}
__device__ __forceinline__ void split4(float4 v, uint2& hi, uint2& lo) {
    __nv_bfloat16 h0 = __float2bfloat16(v.x), h1 = __float2bfloat16(v.y);
    __nv_bfloat16 h2 = __float2bfloat16(v.z), h3 = __float2bfloat16(v.w);
    __nv_bfloat16 l0 = __float2bfloat16(v.x - __bfloat162float(h0));
    __nv_bfloat16 l1 = __float2bfloat16(v.y - __bfloat162float(h1));
    __nv_bfloat16 l2 = __float2bfloat16(v.z - __bfloat162float(h2));
    __nv_bfloat16 l3 = __float2bfloat16(v.w - __bfloat162float(h3));
    hi.x = pk2(h0, h1); hi.y = pk2(h2, h3);
    lo.x = pk2(l0, l1); lo.y = pk2(l2, l3);
}

// ---------------------------------------------------------------------------
// Split-bf16 HMMA GEMM: C[128x64] tile of A[8192x1024] @ W[1024x1024]^T.
// k-chunk = 32 fp32 cols -> smem rows of 64 bf16 (hi cols 0-31 | lo cols 32-63),
// 128 B/row, SW128 xor swizzle (chunk ^= row&7). Double-buffered (48 KB).
// 8 warps: warp grid 4(m) x 2(n), warp tile 32x32, mma m16n8k16.
// zmode: 0 -> Q transposed store *0.125, 1 -> K transposed, 2 -> row-major.
// ---------------------------------------------------------------------------
#define A_TILE_B 16384          // 128 rows * 128 B
#define B_TILE_B 8192           // 64 rows * 128 B
#define STAGE_B  (A_TILE_B + B_TILE_B)

__device__ __forceinline__ uint32_t swz(int row, int chunk16) {
    return (uint32_t)(row * 128 + ((chunk16 ^ (row & 7)) << 4));
}

__device__ void gemm_hmma_body(const float* __restrict__ A,
                               const float* __restrict__ W,
                               const float* __restrict__ bias,
                               int zmode, float* __restrict__ dst)
{
    __shared__ char sm[2 * STAGE_B];   // 49152 B exactly
    const uint32_t sb = smem_u32(sm);

    const int tid  = threadIdx.x;
    const int wid  = tid >> 5;
    const int lane = tid & 31;
    const int bm   = blockIdx.y * 128;
    const int bn   = blockIdx.x * 64;

    const int warp_m = (wid >> 1) * 32;   // 0,32,64,96
    const int warp_n = (wid & 1) * 32;    // 0,32

    // loader mapping: 8 threads per row-slice, float4 col c4
    const int lrow = tid >> 3;            // 0..31
    const int lc4  = (tid & 7) * 4;       // 0,4,...,28
    const uint32_t sA_hi = swz(0, lc4 >> 3) + ((lc4 & 4) << 1);
    const uint32_t sA_lo = swz(0, ((lc4 >> 3) + 4)) + ((lc4 & 4) << 1);
    // note: swz couples chunk with row; compute per-row below instead.

    float c[2][4][4];
    #pragma unroll
    for (int mi = 0; mi < 2; mi++)
        #pragma unroll
        for (int n8 = 0; n8 < 4; n8++)
            #pragma unroll
            for (int q = 0; q < 4; q++) c[mi][n8][q] = 0.f;

    const float* Abase = A + (size_t)bm * DMODEL;
    const float* Wbase = W + (size_t)bn * DMODEL;

    float4 ra[4], rb[2];

    // ---- prologue: load chunk 0 ----
    #pragma unroll
    for (int it = 0; it < 4; it++)
        ra[it] = __ldg((const float4*)&Abase[(size_t)(lrow + it*32) * DMODEL + lc4]);
    #pragma unroll
    for (int it = 0; it < 2; it++)
        rb[it] = __ldg((const float4*)&Wbase[(size_t)(lrow + it*32) * DMODEL + lc4]);

    {
        char* stg = sm;
        #pragma unroll
        for (int it = 0; it < 4; it++) {
            const int row = lrow + it*32;
            uint2 hi, lo; split4(ra[it], hi, lo);
            *(uint2*)(stg + swz(row, lc4 >> 3)       + ((lc4 & 4) << 1)) = hi;
            *(uint2*)(stg + swz(row, (lc4 >> 3) + 4) + ((lc4 & 4) << 1)) = lo;
        }
        #pragma unroll
        for (int it = 0; it < 2; it++) {
            const int row = lrow + it*32;
            uint2 hi, lo; split4(rb[it], hi, lo);
            *(uint2*)(stg + A_TILE_B + swz(row, lc4 >> 3)       + ((lc4 & 4) << 1)) = hi;
            *(uint2*)(stg + A_TILE_B + swz(row, (lc4 >> 3) + 4) + ((lc4 & 4) << 1)) = lo;
        }
    }
    __syncthreads();

    const int lr16 = lane & 15;     // ldmatrix row within 16
    const int lc8  = lane >> 4;     // ldmatrix col8 half (0/1)

    for (int kc = 0; kc < 32; kc++) {
        const int cur = kc & 1;
        const bool more = (kc < 31);
        const int k0n = (kc + 1) * 32;

        if (more) {
            #pragma unroll
            for (int it = 0; it < 4; it++)
                ra[it] = __ldg((const float4*)&Abase[(size_t)(lrow + it*32) * DMODEL + k0n + lc4]);
            #pragma unroll
            for (int it = 0; it < 2; it++)
                rb[it] = __ldg((const float4*)&Wbase[(size_t)(lrow + it*32) * DMODEL + k0n + lc4]);
        }

        // ---- MMA over current stage ----
        const uint32_t aT = sb + cur * STAGE_B;
        const uint32_t bT = aT + A_TILE_B;

        #pragma unroll
        for (int ks = 0; ks < 2; ks++) {
            uint32_t bh[2][4], bl[2][4];
            #pragma unroll
            for (int n16 = 0; n16 < 2; n16++) {
                const int brow = warp_n + n16*16 + lr16;
                ldsm4(bh[n16], bT + swz(brow, (ks*2)     + lc8));
                ldsm4(bl[n16], bT + swz(brow, (4 + ks*2) + lc8));
            }
            #pragma unroll
            for (int mi = 0; mi < 2; mi++) {
                const int arow = warp_m + mi*16 + lr16;
                uint32_t ah[4], al[4];
                ldsm4(ah, aT + swz(arow, (ks*2) + lc8));
                // hi*hi and hi*lo
                #pragma unroll
                for (int n8 = 0; n8 < 4; n8++) {
                    const int n16 = n8 >> 1, pp = n8 & 1;
                    mma16816(c[mi][n8], ah, bh[n16][pp], bh[n16][pp+2]);
                }
                #pragma unroll
                for (int n8 = 0; n8 < 4; n8++) {
                    const int n16 = n8 >> 1, pp = n8 & 1;
                    mma16816(c[mi][n8], ah, bl[n16][pp], bl[n16][pp+2]);
                }
                // lo*hi
                ldsm4(al, aT + swz(arow, (4 + ks*2) + lc8));
                #pragma unroll
                for (int n8 = 0; n8 < 4; n8++) {
                    const int n16 = n8 >> 1, pp = n8 & 1;
                    mma16816(c[mi][n8], al, bh[n16][pp], bh[n16][pp+2]);
                }
            }
        }

        if (more) {
            char* stg = sm + (cur ^ 1) * STAGE_B;
            #pragma unroll
            for (int it = 0; it < 4; it++) {
                const int row = lrow + it*32;
                uint2 hi, lo; split4(ra[it], hi, lo);
                *(uint2*)(stg + swz(row, lc4 >> 3)       + ((lc4 & 4) << 1)) = hi;
                *(uint2*)(stg + swz(row, (lc4 >> 3) + 4) + ((lc4 & 4) << 1)) = lo;
            }
            #pragma unroll
            for (int it = 0; it < 2; it++) {
                const int row = lrow + it*32;
                uint2 hi, lo; split4(rb[it], hi, lo);
                *(uint2*)(stg + A_TILE_B + swz(row, lc4 >> 3)       + ((lc4 & 4) << 1)) = hi;
                *(uint2*)(stg + A_TILE_B + swz(row, (lc4 >> 3) + 4) + ((lc4 & 4) << 1)) = lo;
            }
        }
        __syncthreads();
    }

    // ---- epilogue ----
    const int r0 = lane >> 2;          // 0..7
    const int cc = (lane & 3) * 2;     // 0,2,4,6

    if (zmode == 2) {
        #pragma unroll
        for (int mi = 0; mi < 2; mi++) {
            const int grow = bm + warp_m + mi*16 + r0;
            #pragma unroll
            for (int n8 = 0; n8 < 4; n8++) {
                const int gcol = bn + warp_n + n8*8 + cc;
                const float b0 = bias[gcol], b1 = bias[gcol+1];
                *(float2*)&dst[(size_t)grow * DMODEL + gcol] =
                    make_float2(c[mi][n8][0] + b0, c[mi][n8][1] + b1);
                *(float2*)&dst[(size_t)(grow+8) * DMODEL + gcol] =
                    make_float2(c[mi][n8][2] + b0, c[mi][n8][3] + b1);
            }
        }
    } else {
        const float scale = (zmode == 0) ? 0.125f : 1.0f;
        #pragma unroll
        for (int mi = 0; mi < 2; mi++) {
            const int grow = bm + warp_m + mi*16 + r0;
            const int b0i = grow >> 11, s0 = grow & (SEQ-1);
            const int b1i = (grow+8) >> 11, s1 = (grow+8) & (SEQ-1);
            #pragma unroll
            for (int n8 = 0; n8 < 4; n8++) {
                const int gcol = bn + warp_n + n8*8 + cc;
                const float bb0 = bias[gcol], bb1 = bias[gcol+1];
                dst[((size_t)(b0i*1024 + gcol  ))*SEQ + s0] = (c[mi][n8][0] + bb0) * scale;
                dst[((size_t)(b0i*1024 + gcol+1))*SEQ + s0] = (c[mi][n8][1] + bb1) * scale;
                dst[((size_t)(b1i*1024 + gcol  ))*SEQ + s1] = (c[mi][n8][2] + bb0) * scale;
                dst[((size_t)(b1i*1024 + gcol+1))*SEQ + s1] = (c[mi][n8][3] + bb1) * scale;
            }
        }
    }
}

__global__ void __launch_bounds__(256, 2)
qkv_hmma_kernel(const float* __restrict__ x,
                const float* __restrict__ Wq, const float* __restrict__ bq,
                const float* __restrict__ Wk, const float* __restrict__ bk,
                const float* __restrict__ Wv, const float* __restrict__ bv)
{
    const int z = blockIdx.z;
    const float* W    = (z == 0) ? Wq : (z == 1) ? Wk : Wv;
    const float* bias = (z == 0) ? bq : (z == 1) ? bk : bv;
    float* dst        = (z == 0) ? g_qT : (z == 1) ? g_kT : g_v;
    gemm_hmma_body(x, W, bias, z, dst);
}

__global__ void __launch_bounds__(256, 2)
out_hmma_kernel(const float* __restrict__ Wo, const float* __restrict__ bo,
                float* __restrict__ out)
{
    gemm_hmma_body(g_ctx, Wo, bo, 2, out);
}

// ---------------------------------------------------------------------------
// Flash attention (proven R5 version): two register-tiled GEMMs, 4x4 micro,
// 64x64 S tiles, balanced causal pairing. 48 KB static smem, 2 CTAs/SM.
// ---------------------------------------------------------------------------
__global__ void __launch_bounds__(256, 2) attn_kernel()
{
    __shared__ float Qs [64*64];
    __shared__ float KPs[64*64];
    __shared__ float Vs [64*64];

    const int b  = blockIdx.z;
    const int h  = blockIdx.y;
    const int qp = blockIdx.x;
    const int tid = threadIdx.x;
    const int tx  = tid & 15;
    const int ty  = tid >> 4;
    const int tx4 = tx * 4;
    const int ty4 = ty * 4;

    const size_t headQT = (size_t)(b*1024 + h*DKH) * SEQ;
    const size_t headV  = (size_t)(b*SEQ) * DMODEL + h*DKH;

    for (int half = 0; half < 2; half++) {
        const int qt = half ? (31 - qp) : qp;
        const int q0 = qt * 64;

        __syncthreads();
        #pragma unroll
        for (int it = 0; it < 4; it++) {
            int e  = tid + it * 256;
            int kk = e >> 4;
            int c4 = (e & 15) << 2;
            *(float4*)&Qs[kk*64 + c4] =
                *(const float4*)&g_qT[headQT + (size_t)kk*SEQ + q0 + c4];
        }

        float m[4], l[4], o[4][4];
        #pragma unroll
        for (int i = 0; i < 4; i++) {
            m[i] = -CUDART_INF_F; l[i] = 0.f;
            #pragma unroll
            for (int j = 0; j < 4; j++) o[i][j] = 0.f;
        }

        const int ntiles = qt + 1;
        for (int kt = 0; kt < ntiles; kt++) {
            const int k0 = kt * 64;
            __syncthreads();
            #pragma unroll
            for (int it = 0; it < 4; it++) {
                int e  = tid + it * 256;
                int r  = e >> 4;
                int c4 = (e & 15) << 2;
                *(float4*)&KPs[r*64 + c4] =
                    *(const float4*)&g_kT[headQT + (size_t)r*SEQ + k0 + c4];
                *(float4*)&Vs[r*64 + c4] =
                    *(const float4*)&g_v[headV + (size_t)(k0 + r)*DMODEL + c4];
            }
            __syncthreads();

            float s[4][4];
            #pragma unroll
            for (int i = 0; i < 4; i++)
                #pragma unroll
                for (int j = 0; j < 4; j++) s[i][j] = 0.f;

            #pragma unroll 8
            for (int kk = 0; kk < 64; kk++) {
                float4 q4 = *(const float4*)&Qs [kk*64 + ty4];
                float4 k4 = *(const float4*)&KPs[kk*64 + tx4];
                float qa[4] = {q4.x, q4.y, q4.z, q4.w};
                float ka[4] = {k4.x, k4.y, k4.z, k4.w};
                #pragma unroll
                for (int i = 0; i < 4; i++)
                    #pragma unroll
                    for (int j = 0; j < 4; j++)
                        s[i][j] += qa[i] * ka[j];
            }

            if (kt == qt) {
                #pragma unroll
                for (int i = 0; i < 4; i++)
                    #pragma unroll
                    for (int j = 0; j < 4; j++)
                        if (tx4 + j > ty4 + i) s[i][j] = -CUDART_INF_F;
            }

            #pragma unroll
            for (int i = 0; i < 4; i++) {
                float mx = fmaxf(fmaxf(s[i][0], s[i][1]), fmaxf(s[i][2], s[i][3]));
                mx = fmaxf(mx, __shfl_xor_sync(0xffffffffu, mx, 1));
                mx = fmaxf(mx, __shfl_xor_sync(0xffffffffu, mx, 2));
                mx = fmaxf(mx, __shfl_xor_sync(0xffffffffu, mx, 4));
                mx = fmaxf(mx, __shfl_xor_sync(0xffffffffu, mx, 8));
                float mnew = fmaxf(m[i], mx);
                float corr = __expf(m[i] - mnew);
                float sum = 0.f;
                #pragma unroll
                for (int j = 0; j < 4; j++) {
                    float p = __expf(s[i][j] - mnew);
                    s[i][j] = p;
                    sum += p;
                }
                sum += __shfl_xor_sync(0xffffffffu, sum, 1);
                sum += __shfl_xor_sync(0xffffffffu, sum, 2);
                sum += __shfl_xor_sync(0xffffffffu, sum, 4);
                sum += __shfl_xor_sync(0xffffffffu, sum, 8);
                l[i] = l[i] * corr + sum;
                m[i] = mnew;
                #pragma unroll
                for (int j = 0; j < 4; j++) o[i][j] *= corr;
            }

            __syncthreads();
            #pragma unroll
            for (int i = 0; i < 4; i++)
                *(float4*)&KPs[(ty4 + i)*64 + tx4] =
                    make_float4(s[i][0], s[i][1], s[i][2], s[i][3]);
            __syncthreads();

            #pragma unroll 4
            for (int c4i = 0; c4i < 16; c4i++) {
                const int kk0 = c4i * 4;
                float4 p0 = *(const float4*)&KPs[(ty4+0)*64 + kk0];
                float4 p1 = *(const float4*)&KPs[(ty4+1)*64 + kk0];
                float4 p2 = *(const float4*)&KPs[(ty4+2)*64 + kk0];
                float4 p3 = *(const float4*)&KPs[(ty4+3)*64 + kk0];
                float pr[4][4] = {{p0.x,p0.y,p0.z,p0.w},{p1.x,p1.y,p1.z,p1.w},
                                  {p2.x,p2.y,p2.z,p2.w},{p3.x,p3.y,p3.z,p3.w}};
                #pragma unroll
                for (int cq = 0; cq < 4; cq++) {
                    float4 v4 = *(const float4*)&Vs[(kk0+cq)*64 + tx4];
                    float va[4] = {v4.x, v4.y, v4.z, v4.w};
                    #pragma unroll
                    for (int i = 0; i < 4; i++)
                        #pragma unroll
                        for (int j = 0; j < 4; j++)
                            o[i][j] += pr[i][cq] * va[j];
                }
            }
        }

        #pragma unroll
        for (int i = 0; i < 4; i++) {
            float inv = 1.0f / l[i];
            float4 ov = make_float4(o[i][0]*inv, o[i][1]*inv, o[i][2]*inv, o[i][3]*inv);
            *(float4*)&g_ctx[(size_t)(b*SEQ + q0 + ty4 + i)*DMODEL + h*DKH + tx4] = ov;
        }
    }
}

// ---------------------------------------------------------------------------
extern "C" void kernel_launch(void* const* d_in, const int* in_sizes, int n_in,
                              void* d_out, int out_size)
{
    const float* x  = (const float*)d_in[0];
    const float* Wq = (const float*)d_in[1];
    const float* bq = (const float*)d_in[2];
    const float* Wk = (const float*)d_in[3];
    const float* bk = (const float*)d_in[4];
    const float* Wv = (const float*)d_in[5];
    const float* bv = (const float*)d_in[6];
    const float* Wo = (const float*)d_in[7];
    const float* bo = (const float*)d_in[8];
    float* out = (float*)d_out;

    dim3 gq(DMODEL/64, MROWS/128, 3);
    qkv_hmma_kernel<<<gq, 256>>>(x, Wq, bq, Wk, bk, Wv, bv);

    dim3 ga(16, NHEAD, BATCH);
    attn_kernel<<<ga, 256>>>();

    dim3 go(DMODEL/64, MROWS/128, 1);
    out_hmma_kernel<<<go, 256>>>(Wo, bo, out);
}

// round 17
// speedup vs baseline: 4.5596x; 1.4744x over previous
#include <cuda_runtime.h>
#include <cuda_bf16.h>
#include <math_constants.h>
#include <cstdint>

#define BATCH  4
#define SEQ    2048
#define DMODEL 1024
#define NHEAD  16
#define DKH    64
#define MROWS  (BATCH*SEQ)   // 8192

// Scratch (__device__ globals). Q/K/V stored as split bf16 hi/lo in
// head-major layout [b][h][s][d] (d=64 -> 128-byte rows).
__device__ __nv_bfloat16 g_qh[MROWS*DMODEL];
__device__ __nv_bfloat16 g_ql[MROWS*DMODEL];
__device__ __nv_bfloat16 g_kh[MROWS*DMODEL];
__device__ __nv_bfloat16 g_kl[MROWS*DMODEL];
__device__ __nv_bfloat16 g_vh[MROWS*DMODEL];
__device__ __nv_bfloat16 g_vl[MROWS*DMODEL];
__device__ float g_ctx[MROWS*DMODEL];

// ===========================================================================
// Warp-level MMA helpers (sm_80+ baseline PTX; family-safe on sm_103)
// ===========================================================================
__device__ __forceinline__ uint32_t smem_u32(const void* p) {
    uint32_t a;
    asm("{ .reg .u64 t; cvta.to.shared.u64 t, %1; cvt.u32.u64 %0, t; }"
        : "=r"(a) : "l"(p));
    return a;
}
__device__ __forceinline__ void ldsm4(uint32_t* r, uint32_t addr) {
    asm volatile("ldmatrix.sync.aligned.m8n8.x4.shared.b16 {%0,%1,%2,%3}, [%4];"
        : "=r"(r[0]), "=r"(r[1]), "=r"(r[2]), "=r"(r[3]) : "r"(addr));
}
__device__ __forceinline__ void ldsm4t(uint32_t* r, uint32_t addr) {
    asm volatile("ldmatrix.sync.aligned.m8n8.x4.trans.shared.b16 {%0,%1,%2,%3}, [%4];"
        : "=r"(r[0]), "=r"(r[1]), "=r"(r[2]), "=r"(r[3]) : "r"(addr));
}
__device__ __forceinline__ void mma16816(float* c, const uint32_t* a,
                                         uint32_t b0, uint32_t b1) {
    asm volatile(
        "mma.sync.aligned.m16n8k16.row.col.f32.bf16.bf16.f32 "
        "{%0,%1,%2,%3}, {%4,%5,%6,%7}, {%8,%9}, {%0,%1,%2,%3};"
        : "+f"(c[0]), "+f"(c[1]), "+f"(c[2]), "+f"(c[3])
        : "r"(a[0]), "r"(a[1]), "r"(a[2]), "r"(a[3]), "r"(b0), "r"(b1));
}
__device__ __forceinline__ uint32_t pk2(__nv_bfloat16 a, __nv_bfloat16 b) {
    return (uint32_t)__bfloat16_as_ushort(a) | ((uint32_t)__bfloat16_as_ushort(b) << 16);
}
__device__ __forceinline__ void split4(float4 v, uint2& hi, uint2& lo) {
    __nv_bfloat16 h0 = __float2bfloat16(v.x), h1 = __float2bfloat16(v.y);
    __nv_bfloat16 h2 = __float2bfloat16(v.z), h3 = __float2bfloat16(v.w);
    __nv_bfloat16 l0 = __float2bfloat16(v.x - __bfloat162float(h0));
    __nv_bfloat16 l1 = __float2bfloat16(v.y - __bfloat162float(h1));
    __nv_bfloat16 l2 = __float2bfloat16(v.z - __bfloat162float(h2));
    __nv_bfloat16 l3 = __float2bfloat16(v.w - __bfloat162float(h3));
    hi.x = pk2(h0, h1); hi.y = pk2(h2, h3);
    lo.x = pk2(l0, l1); lo.y = pk2(l2, l3);
}
__device__ __forceinline__ void split_pk(float a, float b, uint32_t& hi, uint32_t& lo) {
    __nv_bfloat16 ha = __float2bfloat16(a), hb = __float2bfloat16(b);
    __nv_bfloat16 la = __float2bfloat16(a - __bfloat162float(ha));
    __nv_bfloat16 lb = __float2bfloat16(b - __bfloat162float(hb));
    hi = pk2(ha, hb); lo = pk2(la, lb);
}
// 128-byte rows, 8 chunks of 16 B, xor swizzle
__device__ __forceinline__ uint32_t swz(int row, int chunk16) {
    return (uint32_t)(row * 128 + ((chunk16 ^ (row & 7)) << 4));
}

// ---------------------------------------------------------------------------
// Split-bf16 HMMA GEMM: C[128x64] tile of A[8192x1024] @ W[1024x1024]^T.
// zmode 0/1/2: write split bf16 hi/lo to head-major Q/K/V (Q scaled 0.125).
// zmode 3: write fp32 + bias row-major to dst (out projection).
// ---------------------------------------------------------------------------
#define A_TILE_B 16384
#define B_TILE_B 8192
#define STAGE_B  (A_TILE_B + B_TILE_B)

__device__ void gemm_hmma_body(const float* __restrict__ A,
                               const float* __restrict__ W,
                               const float* __restrict__ bias,
                               int zmode, float* __restrict__ dst)
{
    __shared__ char sm[2 * STAGE_B];   // 49152 B
    const uint32_t sb = smem_u32(sm);

    const int tid  = threadIdx.x;
    const int wid  = tid >> 5;
    const int lane = tid & 31;
    const int bm   = blockIdx.y * 128;
    const int bn   = blockIdx.x * 64;

    const int warp_m = (wid >> 1) * 32;
    const int warp_n = (wid & 1) * 32;

    const int lrow = tid >> 3;
    const int lc4  = (tid & 7) * 4;

    float c[2][4][4];
    #pragma unroll
    for (int mi = 0; mi < 2; mi++)
        #pragma unroll
        for (int n8 = 0; n8 < 4; n8++)
            #pragma unroll
            for (int q = 0; q < 4; q++) c[mi][n8][q] = 0.f;

    const float* Abase = A + (size_t)bm * DMODEL;
    const float* Wbase = W + (size_t)bn * DMODEL;

    float4 ra[4], rb[2];

    #pragma unroll
    for (int it = 0; it < 4; it++)
        ra[it] = __ldg((const float4*)&Abase[(size_t)(lrow + it*32) * DMODEL + lc4]);
    #pragma unroll
    for (int it = 0; it < 2; it++)
        rb[it] = __ldg((const float4*)&Wbase[(size_t)(lrow + it*32) * DMODEL + lc4]);

    {
        char* stg = sm;
        #pragma unroll
        for (int it = 0; it < 4; it++) {
            const int row = lrow + it*32;
            uint2 hi, lo; split4(ra[it], hi, lo);
            *(uint2*)(stg + swz(row, lc4 >> 3)       + ((lc4 & 4) << 1)) = hi;
            *(uint2*)(stg + swz(row, (lc4 >> 3) + 4) + ((lc4 & 4) << 1)) = lo;
        }
        #pragma unroll
        for (int it = 0; it < 2; it++) {
            const int row = lrow + it*32;
            uint2 hi, lo; split4(rb[it], hi, lo);
            *(uint2*)(stg + A_TILE_B + swz(row, lc4 >> 3)       + ((lc4 & 4) << 1)) = hi;
            *(uint2*)(stg + A_TILE_B + swz(row, (lc4 >> 3) + 4) + ((lc4 & 4) << 1)) = lo;
        }
    }
    __syncthreads();

    const int lr16 = lane & 15;
    const int lc8  = lane >> 4;

    for (int kc = 0; kc < 32; kc++) {
        const int cur = kc & 1;
        const bool more = (kc < 31);
        const int k0n = (kc + 1) * 32;

        if (more) {
            #pragma unroll
            for (int it = 0; it < 4; it++)
                ra[it] = __ldg((const float4*)&Abase[(size_t)(lrow + it*32) * DMODEL + k0n + lc4]);
            #pragma unroll
            for (int it = 0; it < 2; it++)
                rb[it] = __ldg((const float4*)&Wbase[(size_t)(lrow + it*32) * DMODEL + k0n + lc4]);
        }

        const uint32_t aT = sb + cur * STAGE_B;
        const uint32_t bT = aT + A_TILE_B;

        #pragma unroll
        for (int ks = 0; ks < 2; ks++) {
            uint32_t bh[2][4], bl[2][4];
            #pragma unroll
            for (int n16 = 0; n16 < 2; n16++) {
                const int brow = warp_n + n16*16 + lr16;
                ldsm4(bh[n16], bT + swz(brow, (ks*2)     + lc8));
                ldsm4(bl[n16], bT + swz(brow, (4 + ks*2) + lc8));
            }
            #pragma unroll
            for (int mi = 0; mi < 2; mi++) {
                const int arow = warp_m + mi*16 + lr16;
                uint32_t ah[4], al[4];
                ldsm4(ah, aT + swz(arow, (ks*2) + lc8));
                #pragma unroll
                for (int n8 = 0; n8 < 4; n8++) {
                    const int n16 = n8 >> 1, pp = n8 & 1;
                    mma16816(c[mi][n8], ah, bh[n16][pp], bh[n16][pp+2]);
                }
                #pragma unroll
                for (int n8 = 0; n8 < 4; n8++) {
                    const int n16 = n8 >> 1, pp = n8 & 1;
                    mma16816(c[mi][n8], ah, bl[n16][pp], bl[n16][pp+2]);
                }
                ldsm4(al, aT + swz(arow, (4 + ks*2) + lc8));
                #pragma unroll
                for (int n8 = 0; n8 < 4; n8++) {
                    const int n16 = n8 >> 1, pp = n8 & 1;
                    mma16816(c[mi][n8], al, bh[n16][pp], bh[n16][pp+2]);
                }
            }
        }

        if (more) {
            char* stg = sm + (cur ^ 1) * STAGE_B;
            #pragma unroll
            for (int it = 0; it < 4; it++) {
                const int row = lrow + it*32;
                uint2 hi, lo; split4(ra[it], hi, lo);
                *(uint2*)(stg + swz(row, lc4 >> 3)       + ((lc4 & 4) << 1)) = hi;
                *(uint2*)(stg + swz(row, (lc4 >> 3) + 4) + ((lc4 & 4) << 1)) = lo;
            }
            #pragma unroll
            for (int it = 0; it < 2; it++) {
                const int row = lrow + it*32;
                uint2 hi, lo; split4(rb[it], hi, lo);
                *(uint2*)(stg + A_TILE_B + swz(row, lc4 >> 3)       + ((lc4 & 4) << 1)) = hi;
                *(uint2*)(stg + A_TILE_B + swz(row, (lc4 >> 3) + 4) + ((lc4 & 4) << 1)) = lo;
            }
        }
        __syncthreads();
    }

    // ---- epilogue ----
    const int r0 = lane >> 2;
    const int cc = (lane & 3) * 2;

    if (zmode == 3) {
        #pragma unroll
        for (int mi = 0; mi < 2; mi++) {
            const int grow = bm + warp_m + mi*16 + r0;
            #pragma unroll
            for (int n8 = 0; n8 < 4; n8++) {
                const int gcol = bn + warp_n + n8*8 + cc;
                const float b0 = bias[gcol], b1 = bias[gcol+1];
                *(float2*)&dst[(size_t)grow * DMODEL + gcol] =
                    make_float2(c[mi][n8][0] + b0, c[mi][n8][1] + b1);
                *(float2*)&dst[(size_t)(grow+8) * DMODEL + gcol] =
                    make_float2(c[mi][n8][2] + b0, c[mi][n8][3] + b1);
            }
        }
    } else {
        const float scale = (zmode == 0) ? 0.125f : 1.0f;
        __nv_bfloat16* dhi = (zmode == 0) ? g_qh : (zmode == 1) ? g_kh : g_vh;
        __nv_bfloat16* dlo = (zmode == 0) ? g_ql : (zmode == 1) ? g_kl : g_vl;
        #pragma unroll
        for (int mi = 0; mi < 2; mi++) {
            #pragma unroll
            for (int rr = 0; rr < 2; rr++) {
                const int grow = bm + warp_m + mi*16 + r0 + rr*8;
                const int bb = grow >> 11, s = grow & (SEQ-1);
                #pragma unroll
                for (int n8 = 0; n8 < 4; n8++) {
                    const int gcol = bn + warp_n + n8*8 + cc;
                    const int h = gcol >> 6, d = gcol & 63;
                    float y0 = (c[mi][n8][rr*2+0] + bias[gcol])   * scale;
                    float y1 = (c[mi][n8][rr*2+1] + bias[gcol+1]) * scale;
                    uint32_t hi, lo;
                    split_pk(y0, y1, hi, lo);
                    const size_t off = ((size_t)((bb*NHEAD + h)*SEQ + s))*DKH + d;
                    *(uint32_t*)&dhi[off] = hi;
                    *(uint32_t*)&dlo[off] = lo;
                }
            }
        }
    }
}

__global__ void __launch_bounds__(256, 2)
qkv_hmma_kernel(const float* __restrict__ x,
                const float* __restrict__ Wq, const float* __restrict__ bq,
                const float* __restrict__ Wk, const float* __restrict__ bk,
                const float* __restrict__ Wv, const float* __restrict__ bv)
{
    const int z = blockIdx.z;
    const float* W    = (z == 0) ? Wq : (z == 1) ? Wk : Wv;
    const float* bias = (z == 0) ? bq : (z == 1) ? bk : bv;
    gemm_hmma_body(x, W, bias, z, nullptr);
}

__global__ void __launch_bounds__(256, 2)
out_hmma_kernel(const float* __restrict__ Wo, const float* __restrict__ bo,
                float* __restrict__ out)
{
    gemm_hmma_body(g_ctx, Wo, bo, 3, out);
}

// ---------------------------------------------------------------------------
// HMMA flash attention. CTA: 128 Q rows x 64 KV cols per iter, 8 warps,
// warp tile 16(m) x 64(n) -> each warp owns full P rows (accum->A reuse).
// Split bf16 hi/lo on both GEMMs (3 MMA passes each). Causal pairing
// (qp, 15-qp): uniform 34 kv-tiles per CTA. 64 KB dynamic smem.
// ---------------------------------------------------------------------------
#define sQH 0
#define sQL 16384
#define sKH 32768
#define sKL 40960
#define sVH 49152
#define sVL 57344
#define ATT_SMEM 65536

__global__ void __launch_bounds__(256, 2) attn_hmma_kernel()
{
    extern __shared__ char smc[];
    const uint32_t sb = smem_u32(smc);

    const int tid  = threadIdx.x;
    const int wid  = tid >> 5;
    const int lane = tid & 31;
    const int b    = blockIdx.z;
    const int h    = blockIdx.y;
    const int qp   = blockIdx.x;

    const int warp_m = wid * 16;
    const int lr16 = lane & 15;
    const int lc8  = lane >> 4;
    const int quad = lane >> 2;
    const int ql2  = (lane & 3) * 2;

    const size_t headbase = ((size_t)(b*NHEAD + h)) * SEQ * DKH;

    for (int half = 0; half < 2; half++) {
        const int qt = half ? (15 - qp) : qp;
        const int q0 = qt * 128;

        __syncthreads();     // prior half done reading Q
        {   // load Q tile (hi+lo): 128 rows x 128 B each
            const int row = tid >> 1;
            const int cb  = (tid & 1) * 4;
            const size_t g = headbase + (size_t)(q0 + row) * DKH;
            #pragma unroll
            for (int i = 0; i < 4; i++) {
                const int cn = cb + i;
                const uint32_t so = swz(row, cn);
                *(uint4*)(smc + sQH + so) = *(const uint4*)&g_qh[g + cn*8];
                *(uint4*)(smc + sQL + so) = *(const uint4*)&g_ql[g + cn*8];
            }
        }

        float m0 = -CUDART_INF_F, m1 = -CUDART_INF_F, l0 = 0.f, l1 = 0.f;
        float O[8][4];
        #pragma unroll
        for (int n8 = 0; n8 < 8; n8++)
            #pragma unroll
            for (int q = 0; q < 4; q++) O[n8][q] = 0.f;

        const int ntiles = 2 * (qt + 1);
        for (int kt = 0; kt < ntiles; kt++) {
            const int k0 = kt * 64;
            __syncthreads();     // prior compute done reading KV; Q visible
            {   // load K,V tiles (hi+lo): 64 rows x 128 B each
                const int row = tid >> 2;
                const int cb  = (tid & 3) * 2;
                const size_t g = headbase + (size_t)(k0 + row) * DKH;
                #pragma unroll
                for (int i = 0; i < 2; i++) {
                    const int cn = cb + i;
                    const uint32_t so = swz(row, cn);
                    *(uint4*)(smc + sKH + so) = *(const uint4*)&g_kh[g + cn*8];
                    *(uint4*)(smc + sKL + so) = *(const uint4*)&g_kl[g + cn*8];
                    *(uint4*)(smc + sVH + so) = *(const uint4*)&g_vh[g + cn*8];
                    *(uint4*)(smc + sVL + so) = *(const uint4*)&g_vl[g + cn*8];
                }
            }
            __syncthreads();

            // ---- S = Q @ K^T (split: 3 passes) ----
            float S[8][4];
            #pragma unroll
            for (int n8 = 0; n8 < 8; n8++)
                #pragma unroll
                for (int q = 0; q < 4; q++) S[n8][q] = 0.f;

            #pragma unroll
            for (int dk = 0; dk < 4; dk++) {
                uint32_t ah[4], al[4];
                const uint32_t aoff = swz(warp_m + lr16, dk*2 + lc8);
                ldsm4(ah, sb + sQH + aoff);
                ldsm4(al, sb + sQL + aoff);
                #pragma unroll
                for (int n16 = 0; n16 < 4; n16++) {
                    uint32_t kh4[4], kl4[4];
                    const uint32_t boff = swz(n16*16 + lr16, dk*2 + lc8);
                    ldsm4(kh4, sb + sKH + boff);
                    ldsm4(kl4, sb + sKL + boff);
                    #pragma unroll
                    for (int pp = 0; pp < 2; pp++) {
                        const int n8 = n16*2 + pp;
                        mma16816(S[n8], ah, kh4[pp], kh4[pp+2]);
                        mma16816(S[n8], ah, kl4[pp], kl4[pp+2]);
                        mma16816(S[n8], al, kh4[pp], kh4[pp+2]);
                    }
                }
            }

            // ---- causal mask (last two tiles) ----
            if (kt >= 2*qt) {
                const int r0g = q0 + warp_m + quad;
                #pragma unroll
                for (int n8 = 0; n8 < 8; n8++) {
                    const int col = k0 + n8*8 + ql2;
                    if (col     > r0g)     S[n8][0] = -CUDART_INF_F;
                    if (col + 1 > r0g)     S[n8][1] = -CUDART_INF_F;
                    if (col     > r0g + 8) S[n8][2] = -CUDART_INF_F;
                    if (col + 1 > r0g + 8) S[n8][3] = -CUDART_INF_F;
                }
            }

            // ---- online softmax (rows quad, quad+8; reduce over quad lanes) ----
            float mx0 = -CUDART_INF_F, mx1 = -CUDART_INF_F;
            #pragma unroll
            for (int n8 = 0; n8 < 8; n8++) {
                mx0 = fmaxf(mx0, fmaxf(S[n8][0], S[n8][1]));
                mx1 = fmaxf(mx1, fmaxf(S[n8][2], S[n8][3]));
            }
            mx0 = fmaxf(mx0, __shfl_xor_sync(0xffffffffu, mx0, 1));
            mx0 = fmaxf(mx0, __shfl_xor_sync(0xffffffffu, mx0, 2));
            mx1 = fmaxf(mx1, __shfl_xor_sync(0xffffffffu, mx1, 1));
            mx1 = fmaxf(mx1, __shfl_xor_sync(0xffffffffu, mx1, 2));
            const float mn0 = fmaxf(m0, mx0), mn1 = fmaxf(m1, mx1);
            const float cr0 = __expf(m0 - mn0), cr1 = __expf(m1 - mn1);
            m0 = mn0; m1 = mn1;
            float sum0 = 0.f, sum1 = 0.f;
            #pragma unroll
            for (int n8 = 0; n8 < 8; n8++) {
                S[n8][0] = __expf(S[n8][0] - mn0); sum0 += S[n8][0];
                S[n8][1] = __expf(S[n8][1] - mn0); sum0 += S[n8][1];
                S[n8][2] = __expf(S[n8][2] - mn1); sum1 += S[n8][2];
                S[n8][3] = __expf(S[n8][3] - mn1); sum1 += S[n8][3];
            }
            sum0 += __shfl_xor_sync(0xffffffffu, sum0, 1);
            sum0 += __shfl_xor_sync(0xffffffffu, sum0, 2);
            sum1 += __shfl_xor_sync(0xffffffffu, sum1, 1);
            sum1 += __shfl_xor_sync(0xffffffffu, sum1, 2);
            l0 = l0 * cr0 + sum0;
            l1 = l1 * cr1 + sum1;
            #pragma unroll
            for (int n8 = 0; n8 < 8; n8++) {
                O[n8][0] *= cr0; O[n8][1] *= cr0;
                O[n8][2] *= cr1; O[n8][3] *= cr1;
            }

            // ---- O += P @ V (P from accum, split hi/lo; V via trans ldsm).
            // TRANS fragment order is [k0-7/d0-7, k8-15/d0-7, k0-7/d8-15,
            // k8-15/d8-15]: pair (frag[2*pp], frag[2*pp+1]) — NOT (pp, pp+2).
            #pragma unroll
            for (int kc = 0; kc < 4; kc++) {
                uint32_t ph[4], pl[4];
                split_pk(S[2*kc  ][0], S[2*kc  ][1], ph[0], pl[0]);
                split_pk(S[2*kc  ][2], S[2*kc  ][3], ph[1], pl[1]);
                split_pk(S[2*kc+1][0], S[2*kc+1][1], ph[2], pl[2]);
                split_pk(S[2*kc+1][2], S[2*kc+1][3], ph[3], pl[3]);
                #pragma unroll
                for (int n16 = 0; n16 < 4; n16++) {
                    uint32_t vh4[4], vl4[4];
                    const uint32_t voff = swz(kc*16 + lr16, n16*2 + lc8);
                    ldsm4t(vh4, sb + sVH + voff);
                    ldsm4t(vl4, sb + sVL + voff);
                    #pragma unroll
                    for (int pp = 0; pp < 2; pp++) {
                        const int n8 = n16*2 + pp;
                        mma16816(O[n8], ph, vh4[2*pp], vh4[2*pp+1]);
                        mma16816(O[n8], ph, vl4[2*pp], vl4[2*pp+1]);
                        mma16816(O[n8], pl, vh4[2*pp], vh4[2*pp+1]);
                    }
                }
            }
        }

        // ---- epilogue: normalize, write fp32 context ----
        const float inv0 = 1.f / l0, inv1 = 1.f / l1;
        const int r0g = q0 + warp_m + quad;
        const size_t base0 = ((size_t)(b*SEQ + r0g)) * DMODEL + h*DKH + ql2;
        const size_t base1 = base0 + (size_t)8 * DMODEL;
        #pragma unroll
        for (int n8 = 0; n8 < 8; n8++) {
            *(float2*)&g_ctx[base0 + n8*8] =
                make_float2(O[n8][0]*inv0, O[n8][1]*inv0);
            *(float2*)&g_ctx[base1 + n8*8] =
                make_float2(O[n8][2]*inv1, O[n8][3]*inv1);
        }
    }
}

// ---------------------------------------------------------------------------
extern "C" void kernel_launch(void* const* d_in, const int* in_sizes, int n_in,
                              void* d_out, int out_size)
{
    const float* x  = (const float*)d_in[0];
    const float* Wq = (const float*)d_in[1];
    const float* bq = (const float*)d_in[2];
    const float* Wk = (const float*)d_in[3];
    const float* bk = (const float*)d_in[4];
    const float* Wv = (const float*)d_in[5];
    const float* bv = (const float*)d_in[6];
    const float* Wo = (const float*)d_in[7];
    const float* bo = (const float*)d_in[8];
    float* out = (float*)d_out;

    cudaFuncSetAttribute(attn_hmma_kernel,
        cudaFuncAttributeMaxDynamicSharedMemorySize, ATT_SMEM);

    dim3 gq(DMODEL/64, MROWS/128, 3);
    qkv_hmma_kernel<<<gq, 256>>>(x, Wq, bq, Wk, bk, Wv, bv);

    dim3 ga(8, NHEAD, BATCH);
    attn_hmma_kernel<<<ga, 256, ATT_SMEM>>>();

    dim3 go(DMODEL/64, MROWS/128, 1);
    out_hmma_kernel<<<go, 256>>>(Wo, bo, out);
}